// round 2
// baseline (speedup 1.0000x reference)
#include <cuda_runtime.h>
#include <cstdint>

#define N_NODES 50000
#define E_EDGES 1600000
#define D0 512
#define D1 256
#define D2 16

// ---------------- scratch (device globals; no allocation) ----------------
__device__ float g_X1[(size_t)N_NODES * D1];   // H @ W1
__device__ float g_S1[(size_t)N_NODES * D1];   // spmm(X1)
__device__ float g_X2[(size_t)N_NODES * D2];   // relu(S1+b1) @ W2
__device__ float g_S2[(size_t)N_NODES * D2];   // spmm(X2)
__device__ float g_Y [(size_t)N_NODES * D2];   // softmax head
__device__ float g_D [N_NODES];                // degree (weighted)
__device__ float g_Gamma[D2];
__device__ int   g_row[E_EDGES];
__device__ int   g_col[E_EDGES];
__device__ int   g_is32;

// ---------------- index dtype detection + conversion ----------------
__global__ void detect_idx_kernel(const void* ei) {
    // Interpret the first 64 entries as int64. Genuine int64 indices are all
    // in [0, N_NODES). int32 data read as int64 gives lo + hi*2^32 with hi a
    // random index (~0 with prob 2e-5), so out-of-range values appear.
    const long long* p = (const long long*)ei;
    int bad = 0;
    for (int i = 0; i < 64; i++) {
        long long v = p[i];
        if (v < 0 || v >= N_NODES) bad = 1;
    }
    g_is32 = bad;
}

__global__ void convert_idx_kernel(const void* ei, int E) {
    int e = blockIdx.x * blockDim.x + threadIdx.x;
    if (e >= E) return;
    int is32 = g_is32;
    int r, c;
    if (is32) {
        const int* p = (const int*)ei;
        r = p[e];
        c = p[E + e];
    } else {
        const long long* p = (const long long*)ei;
        r = (int)p[e];
        c = (int)p[E + e];
    }
    g_row[e] = r;
    g_col[e] = c;
}

// ---------------- vectorized global reduction ----------------
__device__ __forceinline__ void red_add_v4(float* p, float a, float b, float c, float d) {
    asm volatile("red.global.add.v4.f32 [%0], {%1,%2,%3,%4};"
                 :: "l"(p), "f"(a), "f"(b), "f"(c), "f"(d) : "memory");
}

// ---------------- GEMM1: C[M,256] = A[M,512] @ B[512,256] ----------------
// 64x64 tile, BK=16, 256 threads, 4x4 register micro-tile.
__global__ void gemm1_kernel(const float* __restrict__ A, const float* __restrict__ B,
                             float* __restrict__ C, int M) {
    const int BM = 64, BN = 64, BK = 16;
    __shared__ float As[BK][BM];
    __shared__ float Bs[BK][BN];

    int tid = threadIdx.x;
    int tr = tid >> 4;      // 0..15
    int tc = tid & 15;      // 0..15
    int row0 = blockIdx.y * BM;
    int col0 = blockIdx.x * BN;

    int la_r = tid >> 2;            // 0..63 (A row within tile)
    int la_c = (tid & 3) << 2;      // 0,4,8,12 (A col4 within tile)
    int lb_r = tid >> 4;            // 0..15 (B row within tile)
    int lb_c = (tid & 15) << 2;     // 0..60 (B col4 within tile)

    float acc[4][4] = {};

    for (int k0 = 0; k0 < D0; k0 += BK) {
        float4 av = make_float4(0.f, 0.f, 0.f, 0.f);
        int ar = row0 + la_r;
        if (ar < M) av = *(const float4*)(A + (size_t)ar * D0 + k0 + la_c);
        As[la_c + 0][la_r] = av.x;
        As[la_c + 1][la_r] = av.y;
        As[la_c + 2][la_r] = av.z;
        As[la_c + 3][la_r] = av.w;

        float4 bv = *(const float4*)(B + (size_t)(k0 + lb_r) * D1 + col0 + lb_c);
        *(float4*)&Bs[lb_r][lb_c] = bv;
        __syncthreads();

        #pragma unroll
        for (int kk = 0; kk < BK; kk++) {
            float4 a4 = *(const float4*)&As[kk][tr * 4];
            float4 b4 = *(const float4*)&Bs[kk][tc * 4];
            float av_[4] = {a4.x, a4.y, a4.z, a4.w};
            float bv_[4] = {b4.x, b4.y, b4.z, b4.w};
            #pragma unroll
            for (int i = 0; i < 4; i++)
                #pragma unroll
                for (int j = 0; j < 4; j++)
                    acc[i][j] = fmaf(av_[i], bv_[j], acc[i][j]);
        }
        __syncthreads();
    }

    #pragma unroll
    for (int i = 0; i < 4; i++) {
        int r = row0 + tr * 4 + i;
        if (r < M) {
            float4 v = make_float4(acc[i][0], acc[i][1], acc[i][2], acc[i][3]);
            *(float4*)(C + (size_t)r * D1 + col0 + tc * 4) = v;
        }
    }
}

// ---------------- SpMM d=256: S1[row] += w * X1[col], one warp per edge ----------------
__global__ void spmm256_kernel(const int* __restrict__ ridx,
                               const int* __restrict__ cidx,
                               const float* __restrict__ w,
                               const float* __restrict__ X,
                               float* __restrict__ S, int E) {
    int e = (blockIdx.x * blockDim.x + threadIdx.x) >> 5;
    if (e >= E) return;
    int lane = threadIdx.x & 31;
    int r = ridx[e];
    int c = cidx[e];
    float v = w[e];
    const float4* xc = (const float4*)(X + (size_t)c * D1);
    float* sr = S + (size_t)r * D1;
    #pragma unroll
    for (int i = 0; i < 2; i++) {
        int q = lane + 32 * i;          // 0..63 float4 chunks
        float4 x = xc[q];
        red_add_v4(sr + q * 4, v * x.x, v * x.y, v * x.z, v * x.w);
    }
}

// ---------------- layer2: X2 = relu(S1 + b1) @ W2, one thread per row ----------------
__global__ void layer2_kernel(const float* __restrict__ S1, const float* __restrict__ b1,
                              const float* __restrict__ W2, float* __restrict__ X2, int N) {
    __shared__ float sW[D1 * D2];   // 16 KB
    __shared__ float sb[D1];
    for (int i = threadIdx.x; i < D1 * D2; i += blockDim.x) sW[i] = W2[i];
    for (int i = threadIdx.x; i < D1; i += blockDim.x) sb[i] = b1[i];
    __syncthreads();

    int row = blockIdx.x * blockDim.x + threadIdx.x;
    if (row >= N) return;

    float acc[D2] = {};
    const float4* s = (const float4*)(S1 + (size_t)row * D1);
    #pragma unroll 4
    for (int k4 = 0; k4 < D1 / 4; k4++) {
        float4 v = s[k4];
        int k = k4 * 4;
        float h0 = fmaxf(v.x + sb[k + 0], 0.f);
        float h1 = fmaxf(v.y + sb[k + 1], 0.f);
        float h2 = fmaxf(v.z + sb[k + 2], 0.f);
        float h3 = fmaxf(v.w + sb[k + 3], 0.f);
        #pragma unroll
        for (int j = 0; j < D2; j++) {
            acc[j] = fmaf(h0, sW[(k + 0) * D2 + j],
                     fmaf(h1, sW[(k + 1) * D2 + j],
                     fmaf(h2, sW[(k + 2) * D2 + j],
                     fmaf(h3, sW[(k + 3) * D2 + j], acc[j]))));
        }
    }
    float4* o = (float4*)(X2 + (size_t)row * D2);
    #pragma unroll
    for (int q = 0; q < 4; q++)
        o[q] = make_float4(acc[q * 4 + 0], acc[q * 4 + 1], acc[q * 4 + 2], acc[q * 4 + 3]);
}

// ---------------- SpMM d=16 + degree: 4 threads per edge ----------------
__global__ void spmm16_kernel(const int* __restrict__ ridx,
                              const int* __restrict__ cidx,
                              const float* __restrict__ w,
                              const float* __restrict__ X2,
                              float* __restrict__ S2, float* __restrict__ D, int E) {
    int t = blockIdx.x * blockDim.x + threadIdx.x;
    int e = t >> 2;
    if (e >= E) return;
    int q = t & 3;
    int r = ridx[e];
    int c = cidx[e];
    float v = w[e];
    float4 x = *(const float4*)(X2 + (size_t)c * D2 + q * 4);
    red_add_v4(S2 + (size_t)r * D2 + q * 4, v * x.x, v * x.y, v * x.z, v * x.w);
    if (q == 0) atomicAdd(D + r, v);
}

// ---------------- head: H2=relu(S2+b2); H3=relu(H2@Wl+bl); Y=softmax; Gamma += Y^T D ----------------
__global__ void head_kernel(const float* __restrict__ S2, const float* __restrict__ b2,
                            const float* __restrict__ Wl, const float* __restrict__ bl,
                            const float* __restrict__ D, float* __restrict__ Y,
                            float* __restrict__ Gamma, int N) {
    __shared__ float sW[D2 * D2];
    __shared__ float sb2[D2];
    __shared__ float sbl[D2];
    __shared__ float sG[D2];
    if (threadIdx.x < D2 * D2) sW[threadIdx.x] = Wl[threadIdx.x];
    if (threadIdx.x < D2) {
        sb2[threadIdx.x] = b2[threadIdx.x];
        sbl[threadIdx.x] = bl[threadIdx.x];
        sG[threadIdx.x] = 0.f;
    }
    __syncthreads();

    int row = blockIdx.x * blockDim.x + threadIdx.x;
    if (row < N) {
        float h2[D2];
        const float4* s = (const float4*)(S2 + (size_t)row * D2);
        #pragma unroll
        for (int q = 0; q < 4; q++) {
            float4 v = s[q];
            h2[q * 4 + 0] = fmaxf(v.x + sb2[q * 4 + 0], 0.f);
            h2[q * 4 + 1] = fmaxf(v.y + sb2[q * 4 + 1], 0.f);
            h2[q * 4 + 2] = fmaxf(v.z + sb2[q * 4 + 2], 0.f);
            h2[q * 4 + 3] = fmaxf(v.w + sb2[q * 4 + 3], 0.f);
        }
        float h3[D2];
        #pragma unroll
        for (int j = 0; j < D2; j++) {
            float t = sbl[j];
            #pragma unroll
            for (int k = 0; k < D2; k++) t = fmaf(h2[k], sW[k * D2 + j], t);
            h3[j] = fmaxf(t, 0.f);
        }
        // softmax
        float m = h3[0];
        #pragma unroll
        for (int j = 1; j < D2; j++) m = fmaxf(m, h3[j]);
        float sum = 0.f;
        float y[D2];
        #pragma unroll
        for (int j = 0; j < D2; j++) { y[j] = __expf(h3[j] - m); sum += y[j]; }
        float inv = 1.0f / sum;
        float4* o = (float4*)(Y + (size_t)row * D2);
        #pragma unroll
        for (int q = 0; q < 4; q++) {
            o[q] = make_float4(y[q * 4 + 0] * inv, y[q * 4 + 1] * inv,
                               y[q * 4 + 2] * inv, y[q * 4 + 3] * inv);
        }
        float d = D[row];
        #pragma unroll
        for (int j = 0; j < D2; j++) atomicAdd(&sG[j], y[j] * inv * d);
    }
    __syncthreads();
    if (threadIdx.x < D2) atomicAdd(&Gamma[threadIdx.x], sG[threadIdx.x]);
}

// ---------------- loss: sum_e w_e * dot(Y[r]/Gamma, 1 - Y[c]) ----------------
__global__ void loss_kernel(const int* __restrict__ ridx,
                            const int* __restrict__ cidx,
                            const float* __restrict__ w,
                            const float* __restrict__ Y,
                            const float* __restrict__ Gamma,
                            float* __restrict__ out, int E) {
    __shared__ float sGinv[D2];
    if (threadIdx.x < D2) sGinv[threadIdx.x] = 1.0f / Gamma[threadIdx.x];
    __syncthreads();

    int e = blockIdx.x * blockDim.x + threadIdx.x;
    float acc = 0.f;
    if (e < E) {
        int r = ridx[e];
        int c = cidx[e];
        float v = w[e];
        const float4* yr = (const float4*)(Y + (size_t)r * D2);
        const float4* yc = (const float4*)(Y + (size_t)c * D2);
        #pragma unroll
        for (int q = 0; q < 4; q++) {
            float4 a = yr[q];
            float4 b = yc[q];
            acc += a.x * sGinv[q * 4 + 0] * (1.f - b.x)
                 + a.y * sGinv[q * 4 + 1] * (1.f - b.y)
                 + a.z * sGinv[q * 4 + 2] * (1.f - b.z)
                 + a.w * sGinv[q * 4 + 3] * (1.f - b.w);
        }
        acc *= v;
    }
    // warp reduce, lane0 atomic
    #pragma unroll
    for (int off = 16; off > 0; off >>= 1)
        acc += __shfl_down_sync(0xFFFFFFFFu, acc, off);
    if ((threadIdx.x & 31) == 0) atomicAdd(out, acc);
}

// ---------------- launch ----------------
extern "C" void kernel_launch(void* const* d_in, const int* in_sizes, int n_in,
                              void* d_out, int out_size) {
    const float*     H    = (const float*)d_in[0];
    const void*      ei   = d_in[1];
    const float*     ev   = (const float*)d_in[2];
    const float*     W1   = (const float*)d_in[3];
    const float*     b1   = (const float*)d_in[4];
    const float*     W2   = (const float*)d_in[5];
    const float*     b2   = (const float*)d_in[6];
    const float*     Wl   = (const float*)d_in[7];
    const float*     bl   = (const float*)d_in[8];
    float* out = (float*)d_out;

    int N = in_sizes[0] / D0;          // 50000
    int E = in_sizes[2];               // 1600000

    void *pX1, *pS1, *pX2, *pS2, *pY, *pD, *pG, *pR, *pC;
    cudaGetSymbolAddress(&pX1, g_X1);
    cudaGetSymbolAddress(&pS1, g_S1);
    cudaGetSymbolAddress(&pX2, g_X2);
    cudaGetSymbolAddress(&pS2, g_S2);
    cudaGetSymbolAddress(&pY,  g_Y);
    cudaGetSymbolAddress(&pD,  g_D);
    cudaGetSymbolAddress(&pG,  g_Gamma);
    cudaGetSymbolAddress(&pR,  g_row);
    cudaGetSymbolAddress(&pC,  g_col);
    const int* ridx = (const int*)pR;
    const int* cidx = (const int*)pC;

    // zero accumulators (memset nodes in the graph)
    cudaMemsetAsync(pS1, 0, (size_t)N * D1 * sizeof(float));
    cudaMemsetAsync(pS2, 0, (size_t)N * D2 * sizeof(float));
    cudaMemsetAsync(pD,  0, (size_t)N * sizeof(float));
    cudaMemsetAsync(pG,  0, D2 * sizeof(float));
    cudaMemsetAsync(out, 0, sizeof(float));

    // 0) index dtype detection + conversion to int32
    detect_idx_kernel<<<1, 1>>>(ei);
    convert_idx_kernel<<<(E + 255) / 256, 256>>>(ei, E);

    // 1) X1 = H @ W1
    {
        dim3 grid(D1 / 64, (N + 63) / 64);
        gemm1_kernel<<<grid, 256>>>(H, W1, (float*)pX1, N);
    }
    // 2) S1 = spmm(X1)
    {
        long long threads = (long long)E * 32;
        int blocks = (int)((threads + 255) / 256);
        spmm256_kernel<<<blocks, 256>>>(ridx, cidx, ev, (const float*)pX1, (float*)pS1, E);
    }
    // 3) X2 = relu(S1 + b1) @ W2
    layer2_kernel<<<(N + 255) / 256, 256>>>((const float*)pS1, b1, W2, (float*)pX2, N);
    // 4) S2 = spmm(X2), D = degree
    {
        long long threads = (long long)E * 4;
        int blocks = (int)((threads + 255) / 256);
        spmm16_kernel<<<blocks, 256>>>(ridx, cidx, ev, (const float*)pX2,
                                       (float*)pS2, (float*)pD, E);
    }
    // 5) head: Y, Gamma
    head_kernel<<<(N + 255) / 256, 256>>>((const float*)pS2, b2, Wl, bl,
                                          (const float*)pD, (float*)pY, (float*)pG, N);
    // 6) loss
    loss_kernel<<<(E + 255) / 256, 256>>>(ridx, cidx, ev, (const float*)pY,
                                          (const float*)pG, out, E);
}

// round 3
// speedup vs baseline: 1.1384x; 1.1384x over previous
#include <cuda_runtime.h>
#include <cstdint>

#define N_NODES 50000
#define E_EDGES 1600000
#define D0 512
#define D1 256
#define D2 16

// ---------------- scratch (device globals; no allocation) ----------------
__device__ float g_X1[(size_t)N_NODES * D1];   // H @ W1
__device__ float g_S1[(size_t)N_NODES * D1];   // spmm(X1)
__device__ float g_X2[(size_t)N_NODES * D2];   // relu(S1+b1) @ W2
__device__ float g_S2[(size_t)N_NODES * D2];   // spmm(X2)
__device__ float g_Y [(size_t)N_NODES * D2];   // softmax head
__device__ float g_D [N_NODES];                // degree (weighted)
__device__ float g_Gamma[D2];
__device__ int   g_row[E_EDGES];
__device__ int   g_col[E_EDGES];
__device__ int   g_is32;
// CSR
__device__ int   g_cnt[N_NODES];               // histogram (zeroed each replay)
__device__ int   g_rowptr[N_NODES + 1];
__device__ int   g_ofs[N_NODES];               // scatter cursors
__device__ unsigned long long g_edge[E_EDGES]; // packed (col | w<<32), row-sorted

// ---------------- index dtype detection ----------------
__global__ void detect_idx_kernel(const void* ei) {
    const long long* p = (const long long*)ei;
    int bad = 0;
    for (int i = 0; i < 64; i++) {
        long long v = p[i];
        if (v < 0 || v >= N_NODES) bad = 1;
    }
    g_is32 = bad;
}

// convert to int32 + row histogram
__global__ void convert_idx_kernel(const void* ei, int E) {
    int e = blockIdx.x * blockDim.x + threadIdx.x;
    if (e >= E) return;
    int is32 = g_is32;
    int r, c;
    if (is32) {
        const int* p = (const int*)ei;
        r = p[e];
        c = p[E + e];
    } else {
        const long long* p = (const long long*)ei;
        r = (int)p[e];
        c = (int)p[E + e];
    }
    g_row[e] = r;
    g_col[e] = c;
    atomicAdd(&g_cnt[r], 1);
}

// ---------------- exclusive scan over g_cnt -> g_rowptr, g_ofs (1 block, 1024 thr) ----------------
__global__ void scan_kernel(int N, int E) {
    __shared__ int wsum[32];
    int tid = threadIdx.x;
    const int chunk = (N + 1023) / 1024;
    int start = tid * chunk;
    int end = min(start + chunk, N);

    int s = 0;
    for (int i = start; i < end; i++) s += g_cnt[i];

    // inclusive scan of s over 1024 threads
    int lane = tid & 31, wid = tid >> 5;
    int v = s;
    #pragma unroll
    for (int off = 1; off < 32; off <<= 1) {
        int t = __shfl_up_sync(0xFFFFFFFFu, v, off);
        if (lane >= off) v += t;
    }
    if (lane == 31) wsum[wid] = v;
    __syncthreads();
    if (wid == 0) {
        int w = wsum[lane];
        #pragma unroll
        for (int off = 1; off < 32; off <<= 1) {
            int t = __shfl_up_sync(0xFFFFFFFFu, w, off);
            if (lane >= off) w += t;
        }
        wsum[lane] = w;
    }
    __syncthreads();
    int excl = v - s + (wid > 0 ? wsum[wid - 1] : 0);

    int run = excl;
    for (int i = start; i < end; i++) {
        g_rowptr[i] = run;
        g_ofs[i] = run;
        run += g_cnt[i];
    }
    if (tid == 1023) g_rowptr[N] = E;
}

// ---------------- scatter edges into CSR order ----------------
__global__ void scatter_kernel(const float* __restrict__ w, int E) {
    int e = blockIdx.x * blockDim.x + threadIdx.x;
    if (e >= E) return;
    int r = g_row[e];
    int pos = atomicAdd(&g_ofs[r], 1);
    unsigned long long packed =
        ((unsigned long long)__float_as_uint(w[e]) << 32) | (unsigned)g_col[e];
    g_edge[pos] = packed;
}

// ---------------- GEMM1: C[M,256] = A[M,512] @ B[512,256] ----------------
// 128x128 tile, BK=8, 256 threads, 8x8 register micro-tile.
__global__ void __launch_bounds__(256, 2)
gemm1_kernel(const float* __restrict__ A, const float* __restrict__ B,
             float* __restrict__ C, int M) {
    const int BM = 128, BN = 128, BK = 8;
    __shared__ float As[BK][BM];
    __shared__ float Bs[BK][BN];

    int tid = threadIdx.x;
    int row0 = blockIdx.y * BM;
    int col0 = blockIdx.x * BN;
    int tr = tid >> 4;              // 0..15 -> rows tr*8..tr*8+7
    int tc = tid & 15;              // 0..15 -> cols tc*8..tc*8+7

    int ar_l = tid >> 1;            // 0..127
    int ac_l = (tid & 1) * 4;       // 0 or 4
    int br_l = tid >> 5;            // 0..7
    int bc_l = (tid & 31) * 4;      // 0..124

    float acc[8][8] = {};

    for (int k0 = 0; k0 < D0; k0 += BK) {
        float4 av = make_float4(0.f, 0.f, 0.f, 0.f);
        int ar = row0 + ar_l;
        if (ar < M) av = *(const float4*)(A + (size_t)ar * D0 + k0 + ac_l);
        As[ac_l + 0][ar_l] = av.x;
        As[ac_l + 1][ar_l] = av.y;
        As[ac_l + 2][ar_l] = av.z;
        As[ac_l + 3][ar_l] = av.w;

        float4 bv = *(const float4*)(B + (size_t)(k0 + br_l) * D1 + col0 + bc_l);
        *(float4*)&Bs[br_l][bc_l] = bv;
        __syncthreads();

        #pragma unroll
        for (int kk = 0; kk < BK; kk++) {
            float4 a0 = *(const float4*)&As[kk][tr * 8];
            float4 a1 = *(const float4*)&As[kk][tr * 8 + 4];
            float4 b0 = *(const float4*)&Bs[kk][tc * 8];
            float4 b1 = *(const float4*)&Bs[kk][tc * 8 + 4];
            float a[8] = {a0.x, a0.y, a0.z, a0.w, a1.x, a1.y, a1.z, a1.w};
            float b[8] = {b0.x, b0.y, b0.z, b0.w, b1.x, b1.y, b1.z, b1.w};
            #pragma unroll
            for (int i = 0; i < 8; i++)
                #pragma unroll
                for (int j = 0; j < 8; j++)
                    acc[i][j] = fmaf(a[i], b[j], acc[i][j]);
        }
        __syncthreads();
    }

    #pragma unroll
    for (int i = 0; i < 8; i++) {
        int r = row0 + tr * 8 + i;
        if (r < M) {
            float* cp = C + (size_t)r * D1 + col0 + tc * 8;
            *(float4*)cp = make_float4(acc[i][0], acc[i][1], acc[i][2], acc[i][3]);
            *(float4*)(cp + 4) = make_float4(acc[i][4], acc[i][5], acc[i][6], acc[i][7]);
        }
    }
}

// ---------------- SpMM d=256 (CSR): 64 threads per row, no atomics ----------------
__global__ void spmm256_csr_kernel(const float* __restrict__ X,
                                   float* __restrict__ S, int N) {
    int row = blockIdx.x * 4 + (threadIdx.x >> 6);
    if (row >= N) return;
    int lane = threadIdx.x & 63;            // handles 4 floats
    int beg = g_rowptr[row];
    int end = g_rowptr[row + 1];

    float4 acc = make_float4(0.f, 0.f, 0.f, 0.f);
    int e = beg;
    for (; e + 4 <= end; e += 4) {
        #pragma unroll
        for (int u = 0; u < 4; u++) {
            unsigned long long p = g_edge[e + u];
            int c = (int)(p & 0xFFFFFFFFull);
            float v = __uint_as_float((unsigned)(p >> 32));
            float4 x = *(const float4*)(X + (size_t)c * D1 + lane * 4);
            acc.x = fmaf(v, x.x, acc.x);
            acc.y = fmaf(v, x.y, acc.y);
            acc.z = fmaf(v, x.z, acc.z);
            acc.w = fmaf(v, x.w, acc.w);
        }
    }
    for (; e < end; e++) {
        unsigned long long p = g_edge[e];
        int c = (int)(p & 0xFFFFFFFFull);
        float v = __uint_as_float((unsigned)(p >> 32));
        float4 x = *(const float4*)(X + (size_t)c * D1 + lane * 4);
        acc.x = fmaf(v, x.x, acc.x);
        acc.y = fmaf(v, x.y, acc.y);
        acc.z = fmaf(v, x.z, acc.z);
        acc.w = fmaf(v, x.w, acc.w);
    }
    *(float4*)(S + (size_t)row * D1 + lane * 4) = acc;
}

// ---------------- layer2: X2 = relu(S1 + b1) @ W2, one thread per row ----------------
__global__ void layer2_kernel(const float* __restrict__ S1, const float* __restrict__ b1,
                              const float* __restrict__ W2, float* __restrict__ X2, int N) {
    __shared__ float sW[D1 * D2];   // 16 KB
    __shared__ float sb[D1];
    for (int i = threadIdx.x; i < D1 * D2; i += blockDim.x) sW[i] = W2[i];
    for (int i = threadIdx.x; i < D1; i += blockDim.x) sb[i] = b1[i];
    __syncthreads();

    int row = blockIdx.x * blockDim.x + threadIdx.x;
    if (row >= N) return;

    float acc[D2] = {};
    const float4* s = (const float4*)(S1 + (size_t)row * D1);
    #pragma unroll 4
    for (int k4 = 0; k4 < D1 / 4; k4++) {
        float4 v = s[k4];
        int k = k4 * 4;
        float h0 = fmaxf(v.x + sb[k + 0], 0.f);
        float h1 = fmaxf(v.y + sb[k + 1], 0.f);
        float h2 = fmaxf(v.z + sb[k + 2], 0.f);
        float h3 = fmaxf(v.w + sb[k + 3], 0.f);
        #pragma unroll
        for (int j = 0; j < D2; j++) {
            acc[j] = fmaf(h0, sW[(k + 0) * D2 + j],
                     fmaf(h1, sW[(k + 1) * D2 + j],
                     fmaf(h2, sW[(k + 2) * D2 + j],
                     fmaf(h3, sW[(k + 3) * D2 + j], acc[j]))));
        }
    }
    float4* o = (float4*)(X2 + (size_t)row * D2);
    #pragma unroll
    for (int q = 0; q < 4; q++)
        o[q] = make_float4(acc[q * 4 + 0], acc[q * 4 + 1], acc[q * 4 + 2], acc[q * 4 + 3]);
}

// ---------------- SpMM d=16 + degree (CSR): 16 threads per row, no atomics ----------------
__global__ void spmm16_csr_kernel(const float* __restrict__ X2,
                                  float* __restrict__ S2, float* __restrict__ D, int N) {
    int row = blockIdx.x * 16 + (threadIdx.x >> 4);
    if (row >= N) return;
    int j = threadIdx.x & 15;
    int beg = g_rowptr[row];
    int end = g_rowptr[row + 1];

    float acc = 0.f, wsum = 0.f;
    for (int e = beg; e < end; e++) {
        unsigned long long p = g_edge[e];
        int c = (int)(p & 0xFFFFFFFFull);
        float v = __uint_as_float((unsigned)(p >> 32));
        acc = fmaf(v, X2[(size_t)c * D2 + j], acc);
        wsum += v;
    }
    S2[(size_t)row * D2 + j] = acc;
    if (j == 0) D[row] = wsum;
}

// ---------------- head: H2=relu(S2+b2); H3=relu(H2@Wl+bl); Y=softmax; Gamma += Y^T D ----------------
__global__ void head_kernel(const float* __restrict__ S2, const float* __restrict__ b2,
                            const float* __restrict__ Wl, const float* __restrict__ bl,
                            const float* __restrict__ D, float* __restrict__ Y,
                            float* __restrict__ Gamma, int N) {
    __shared__ float sW[D2 * D2];
    __shared__ float sb2[D2];
    __shared__ float sbl[D2];
    __shared__ float sG[D2];
    if (threadIdx.x < D2 * D2) sW[threadIdx.x] = Wl[threadIdx.x];
    if (threadIdx.x < D2) {
        sb2[threadIdx.x] = b2[threadIdx.x];
        sbl[threadIdx.x] = bl[threadIdx.x];
        sG[threadIdx.x] = 0.f;
    }
    __syncthreads();

    int row = blockIdx.x * blockDim.x + threadIdx.x;
    if (row < N) {
        float h2[D2];
        const float4* s = (const float4*)(S2 + (size_t)row * D2);
        #pragma unroll
        for (int q = 0; q < 4; q++) {
            float4 v = s[q];
            h2[q * 4 + 0] = fmaxf(v.x + sb2[q * 4 + 0], 0.f);
            h2[q * 4 + 1] = fmaxf(v.y + sb2[q * 4 + 1], 0.f);
            h2[q * 4 + 2] = fmaxf(v.z + sb2[q * 4 + 2], 0.f);
            h2[q * 4 + 3] = fmaxf(v.w + sb2[q * 4 + 3], 0.f);
        }
        float h3[D2];
        #pragma unroll
        for (int j = 0; j < D2; j++) {
            float t = sbl[j];
            #pragma unroll
            for (int k = 0; k < D2; k++) t = fmaf(h2[k], sW[k * D2 + j], t);
            h3[j] = fmaxf(t, 0.f);
        }
        float m = h3[0];
        #pragma unroll
        for (int j = 1; j < D2; j++) m = fmaxf(m, h3[j]);
        float sum = 0.f;
        float y[D2];
        #pragma unroll
        for (int j = 0; j < D2; j++) { y[j] = __expf(h3[j] - m); sum += y[j]; }
        float inv = 1.0f / sum;
        float4* o = (float4*)(Y + (size_t)row * D2);
        #pragma unroll
        for (int q = 0; q < 4; q++) {
            o[q] = make_float4(y[q * 4 + 0] * inv, y[q * 4 + 1] * inv,
                               y[q * 4 + 2] * inv, y[q * 4 + 3] * inv);
        }
        float d = D[row];
        #pragma unroll
        for (int j = 0; j < D2; j++) atomicAdd(&sG[j], y[j] * inv * d);
    }
    __syncthreads();
    if (threadIdx.x < D2) atomicAdd(&Gamma[threadIdx.x], sG[threadIdx.x]);
}

// ---------------- loss: sum_e w_e * dot(Y[r]/Gamma, 1 - Y[c]) ----------------
__global__ void loss_kernel(const int* __restrict__ ridx,
                            const int* __restrict__ cidx,
                            const float* __restrict__ w,
                            const float* __restrict__ Y,
                            const float* __restrict__ Gamma,
                            float* __restrict__ out, int E) {
    __shared__ float sGinv[D2];
    if (threadIdx.x < D2) sGinv[threadIdx.x] = 1.0f / Gamma[threadIdx.x];
    __syncthreads();

    int e = blockIdx.x * blockDim.x + threadIdx.x;
    float acc = 0.f;
    if (e < E) {
        int r = ridx[e];
        int c = cidx[e];
        float v = w[e];
        const float4* yr = (const float4*)(Y + (size_t)r * D2);
        const float4* yc = (const float4*)(Y + (size_t)c * D2);
        #pragma unroll
        for (int q = 0; q < 4; q++) {
            float4 a = yr[q];
            float4 b = yc[q];
            acc += a.x * sGinv[q * 4 + 0] * (1.f - b.x)
                 + a.y * sGinv[q * 4 + 1] * (1.f - b.y)
                 + a.z * sGinv[q * 4 + 2] * (1.f - b.z)
                 + a.w * sGinv[q * 4 + 3] * (1.f - b.w);
        }
        acc *= v;
    }
    #pragma unroll
    for (int off = 16; off > 0; off >>= 1)
        acc += __shfl_down_sync(0xFFFFFFFFu, acc, off);
    if ((threadIdx.x & 31) == 0) atomicAdd(out, acc);
}

// ---------------- launch ----------------
extern "C" void kernel_launch(void* const* d_in, const int* in_sizes, int n_in,
                              void* d_out, int out_size) {
    const float*     H    = (const float*)d_in[0];
    const void*      ei   = d_in[1];
    const float*     ev   = (const float*)d_in[2];
    const float*     W1   = (const float*)d_in[3];
    const float*     b1   = (const float*)d_in[4];
    const float*     W2   = (const float*)d_in[5];
    const float*     b2   = (const float*)d_in[6];
    const float*     Wl   = (const float*)d_in[7];
    const float*     bl   = (const float*)d_in[8];
    float* out = (float*)d_out;

    int N = in_sizes[0] / D0;          // 50000
    int E = in_sizes[2];               // 1600000

    void *pX1, *pS1, *pX2, *pS2, *pY, *pD, *pG, *pR, *pC, *pCnt;
    cudaGetSymbolAddress(&pX1, g_X1);
    cudaGetSymbolAddress(&pS1, g_S1);
    cudaGetSymbolAddress(&pX2, g_X2);
    cudaGetSymbolAddress(&pS2, g_S2);
    cudaGetSymbolAddress(&pY,  g_Y);
    cudaGetSymbolAddress(&pD,  g_D);
    cudaGetSymbolAddress(&pG,  g_Gamma);
    cudaGetSymbolAddress(&pR,  g_row);
    cudaGetSymbolAddress(&pC,  g_col);
    cudaGetSymbolAddress(&pCnt, g_cnt);
    const int* ridx = (const int*)pR;
    const int* cidx = (const int*)pC;

    cudaMemsetAsync(pCnt, 0, N_NODES * sizeof(int));
    cudaMemsetAsync(pG,  0, D2 * sizeof(float));
    cudaMemsetAsync(out, 0, sizeof(float));

    // 0) index convert + histogram, scan, scatter -> CSR
    detect_idx_kernel<<<1, 1>>>(ei);
    convert_idx_kernel<<<(E + 255) / 256, 256>>>(ei, E);
    scan_kernel<<<1, 1024>>>(N, E);
    scatter_kernel<<<(E + 255) / 256, 256>>>(ev, E);

    // 1) X1 = H @ W1
    {
        dim3 grid(D1 / 128, (N + 127) / 128);
        gemm1_kernel<<<grid, 256>>>(H, W1, (float*)pX1, N);
    }
    // 2) S1 = spmm(X1), CSR segment-sum
    spmm256_csr_kernel<<<(N + 3) / 4, 256>>>((const float*)pX1, (float*)pS1, N);
    // 3) X2 = relu(S1 + b1) @ W2
    layer2_kernel<<<(N + 255) / 256, 256>>>((const float*)pS1, b1, W2, (float*)pX2, N);
    // 4) S2 = spmm(X2), D = degree (CSR)
    spmm16_csr_kernel<<<(N + 15) / 16, 256>>>((const float*)pX2, (float*)pS2, (float*)pD, N);
    // 5) head: Y, Gamma
    head_kernel<<<(N + 255) / 256, 256>>>((const float*)pS2, b2, Wl, bl,
                                          (const float*)pD, (float*)pY, (float*)pG, N);
    // 6) loss
    loss_kernel<<<(E + 255) / 256, 256>>>(ridx, cidx, ev, (const float*)pY,
                                          (const float*)pG, out, E);
}

// round 5
// speedup vs baseline: 1.2743x; 1.1194x over previous
#include <cuda_runtime.h>
#include <cstdint>

#define N_NODES 50000
#define E_EDGES 1600000
#define D0 512
#define D1 256
#define D2 16

// ---------------- scratch (device globals; no allocation) ----------------
__device__ float g_X1[(size_t)N_NODES * D1];   // H @ W1
__device__ float g_S1[(size_t)N_NODES * D1];   // spmm(X1)
__device__ float g_X2[(size_t)N_NODES * D2];   // relu(S1+b1) @ W2
__device__ float g_S2[(size_t)N_NODES * D2];   // spmm(X2)
__device__ float g_Y [(size_t)N_NODES * D2];   // softmax head
__device__ float g_D [N_NODES];                // degree (weighted)
__device__ float g_Gamma[D2];
__device__ float g_W1T[(size_t)D1 * D0];       // W1 transposed: [256][512] K-major
__device__ int   g_row[E_EDGES];
__device__ int   g_col[E_EDGES];
__device__ int   g_is32;
// CSR
__device__ int   g_cnt[N_NODES];
__device__ int   g_rowptr[N_NODES + 1];
__device__ int   g_ofs[N_NODES];
__device__ unsigned long long g_edge[E_EDGES];

// ================= helpers (all arch-agnostic PTX, sm_80+) =================
__device__ __forceinline__ uint32_t smem_u32(const void* p) {
    uint32_t a;
    asm("{ .reg .u64 t; cvta.to.shared.u64 t, %1; cvt.u32.u64 %0, t; }" : "=r"(a) : "l"(p));
    return a;
}
__device__ __forceinline__ void cp_async16(uint32_t saddr, const void* g, int srcbytes) {
    asm volatile("cp.async.cg.shared.global [%0], [%1], 16, %2;"
                 :: "r"(saddr), "l"(g), "r"(srcbytes) : "memory");
}
__device__ __forceinline__ uint32_t tf32_hi(float a) {
    uint32_t r;
    asm("cvt.rna.tf32.f32 %0, %1;" : "=r"(r) : "f"(a));
    return r;
}
__device__ __forceinline__ void mma_tf32(float* c, const uint32_t* a, const uint32_t* b) {
    asm volatile(
        "mma.sync.aligned.m16n8k8.row.col.f32.tf32.tf32.f32 "
        "{%0,%1,%2,%3}, {%4,%5,%6,%7}, {%8,%9}, {%0,%1,%2,%3};"
        : "+f"(c[0]), "+f"(c[1]), "+f"(c[2]), "+f"(c[3])
        : "r"(a[0]), "r"(a[1]), "r"(a[2]), "r"(a[3]), "r"(b[0]), "r"(b[1]));
}

// ---------------- index dtype detection ----------------
__global__ void detect_idx_kernel(const void* ei) {
    const long long* p = (const long long*)ei;
    int bad = 0;
    for (int i = 0; i < 64; i++) {
        long long v = p[i];
        if (v < 0 || v >= N_NODES) bad = 1;
    }
    g_is32 = bad;
}

__global__ void convert_idx_kernel(const void* ei, int E) {
    int e = blockIdx.x * blockDim.x + threadIdx.x;
    if (e >= E) return;
    int is32 = g_is32;
    int r, c;
    if (is32) {
        const int* p = (const int*)ei;
        r = p[e]; c = p[E + e];
    } else {
        const long long* p = (const long long*)ei;
        r = (int)p[e]; c = (int)p[E + e];
    }
    g_row[e] = r;
    g_col[e] = c;
    atomicAdd(&g_cnt[r], 1);
}

__global__ void scan_kernel(int N, int E) {
    __shared__ int wsum[32];
    int tid = threadIdx.x;
    const int chunk = (N + 1023) / 1024;
    int start = tid * chunk;
    int end = min(start + chunk, N);
    int s = 0;
    for (int i = start; i < end; i++) s += g_cnt[i];
    int lane = tid & 31, wid = tid >> 5;
    int v = s;
    #pragma unroll
    for (int off = 1; off < 32; off <<= 1) {
        int t = __shfl_up_sync(0xFFFFFFFFu, v, off);
        if (lane >= off) v += t;
    }
    if (lane == 31) wsum[wid] = v;
    __syncthreads();
    if (wid == 0) {
        int w = wsum[lane];
        #pragma unroll
        for (int off = 1; off < 32; off <<= 1) {
            int t = __shfl_up_sync(0xFFFFFFFFu, w, off);
            if (lane >= off) w += t;
        }
        wsum[lane] = w;
    }
    __syncthreads();
    int excl = v - s + (wid > 0 ? wsum[wid - 1] : 0);
    int run = excl;
    for (int i = start; i < end; i++) {
        g_rowptr[i] = run;
        g_ofs[i] = run;
        run += g_cnt[i];
    }
    if (tid == 1023) g_rowptr[N] = E;
}

__global__ void scatter_kernel(const float* __restrict__ w, int E) {
    int e = blockIdx.x * blockDim.x + threadIdx.x;
    if (e >= E) return;
    int r = g_row[e];
    int pos = atomicAdd(&g_ofs[r], 1);
    unsigned long long packed =
        ((unsigned long long)__float_as_uint(w[e]) << 32) | (unsigned)g_col[e];
    g_edge[pos] = packed;
}

// ---------------- W1 transpose: [512][256] -> [256][512] ----------------
__global__ void transpose_w1(const float* __restrict__ W1, float* __restrict__ BT) {
    __shared__ float t[32][33];
    int x = blockIdx.x * 32 + threadIdx.x;   // n
    int y = blockIdx.y * 32 + threadIdx.y;   // k
    #pragma unroll
    for (int j = 0; j < 32; j += 8)
        t[threadIdx.y + j][threadIdx.x] = W1[(size_t)(y + j) * D1 + x];
    __syncthreads();
    int x2 = blockIdx.y * 32 + threadIdx.x;  // k
    int y2 = blockIdx.x * 32 + threadIdx.y;  // n
    #pragma unroll
    for (int j = 0; j < 32; j += 8)
        BT[(size_t)(y2 + j) * D0 + x2] = t[threadIdx.x][threadIdx.y + j];
}

// ---------------- GEMM1: mma.sync tf32, 3-pass split precision ----------------
// C[M,256] = A[M,512] @ BT[256,512]^T
// 128x128 block tile, 8 warps (2x4) each 64x32, BK=16, cp.async double buffer.
#define BK 16
#define AST 20   // padded smem stride (floats): 16B-aligned, conflict-free frags

__global__ void __launch_bounds__(256, 1)
gemm1_mma_kernel(const float* __restrict__ A, const float* __restrict__ BT,
                 float* __restrict__ C, int M) {
    __shared__ float As[2][128 * AST];
    __shared__ float Bs[2][128 * AST];

    int tid = threadIdx.x;
    int lane = tid & 31, wid = tid >> 5;
    int gid = lane >> 2, tig = lane & 3;
    int warp_m = (wid & 1) * 64;
    int warp_n = (wid >> 1) * 32;
    int row0 = blockIdx.y * 128;
    int col0 = blockIdx.x * 128;

    int lr = tid >> 2;          // 0..63
    int lc = (tid & 3) * 4;     // 0,4,8,12

    float acc[4][4][4] = {};

    const int NI = D0 / BK;     // 32

    // ---- stage loader ----
    auto load_stage = [&](int s, int i) {
        int k0 = i * BK;
        #pragma unroll
        for (int h = 0; h < 2; h++) {
            int r = lr + h * 64;
            int gr = row0 + r;
            cp_async16(smem_u32(&As[s][r * AST + lc]),
                       A + (size_t)gr * D0 + k0 + lc, gr < M ? 16 : 0);
        }
        #pragma unroll
        for (int h = 0; h < 2; h++) {
            int n = lr + h * 64;
            cp_async16(smem_u32(&Bs[s][n * AST + lc]),
                       BT + (size_t)(col0 + n) * D0 + k0 + lc, 16);
        }
    };

    load_stage(0, 0);
    asm volatile("cp.async.commit_group;");

    for (int i = 0; i < NI; i++) {
        int s = i & 1;
        if (i + 1 < NI) {
            load_stage((i + 1) & 1, i + 1);
            asm volatile("cp.async.commit_group;");
            asm volatile("cp.async.wait_group 1;");
        } else {
            asm volatile("cp.async.wait_group 0;");
        }
        __syncthreads();

        #pragma unroll
        for (int ks = 0; ks < 2; ks++) {
            int k0 = ks * 8;
            float a[4][4], b[4][2];
            #pragma unroll
            for (int t = 0; t < 4; t++) {
                int rb = warp_m + t * 16 + gid;
                a[t][0] = As[s][(rb)     * AST + k0 + tig];
                a[t][1] = As[s][(rb + 8) * AST + k0 + tig];
                a[t][2] = As[s][(rb)     * AST + k0 + tig + 4];
                a[t][3] = As[s][(rb + 8) * AST + k0 + tig + 4];
            }
            #pragma unroll
            for (int u = 0; u < 4; u++) {
                int nb = warp_n + u * 8 + gid;
                b[u][0] = Bs[s][nb * AST + k0 + tig];
                b[u][1] = Bs[s][nb * AST + k0 + tig + 4];
            }

            uint32_t ah[4][4], al[4][4], bh[4][2], bl[4][2];
            #pragma unroll
            for (int t = 0; t < 4; t++)
                #pragma unroll
                for (int q = 0; q < 4; q++) {
                    ah[t][q] = tf32_hi(a[t][q]);
                    al[t][q] = tf32_hi(a[t][q] - __uint_as_float(ah[t][q]));
                }
            #pragma unroll
            for (int u = 0; u < 4; u++)
                #pragma unroll
                for (int q = 0; q < 2; q++) {
                    bh[u][q] = tf32_hi(b[u][q]);
                    bl[u][q] = tf32_hi(b[u][q] - __uint_as_float(bh[u][q]));
                }

            // pass 1: Ah*Bh
            #pragma unroll
            for (int t = 0; t < 4; t++)
                #pragma unroll
                for (int u = 0; u < 4; u++)
                    mma_tf32(acc[t][u], ah[t], bh[u]);
            // pass 2: Ah*Bl
            #pragma unroll
            for (int t = 0; t < 4; t++)
                #pragma unroll
                for (int u = 0; u < 4; u++)
                    mma_tf32(acc[t][u], ah[t], bl[u]);
            // pass 3: Al*Bh
            #pragma unroll
            for (int t = 0; t < 4; t++)
                #pragma unroll
                for (int u = 0; u < 4; u++)
                    mma_tf32(acc[t][u], al[t], bh[u]);
        }
        __syncthreads();
    }

    // ---- epilogue ----
    #pragma unroll
    for (int t = 0; t < 4; t++) {
        int r_lo = row0 + warp_m + t * 16 + gid;
        int r_hi = r_lo + 8;
        #pragma unroll
        for (int u = 0; u < 4; u++) {
            int cc = col0 + warp_n + u * 8 + tig * 2;
            if (r_lo < M)
                *(float2*)(C + (size_t)r_lo * D1 + cc) =
                    make_float2(acc[t][u][0], acc[t][u][1]);
            if (r_hi < M)
                *(float2*)(C + (size_t)r_hi * D1 + cc) =
                    make_float2(acc[t][u][2], acc[t][u][3]);
        }
    }
}

// ---------------- SpMM d=256 (CSR): 64 threads per row, no atomics ----------------
__global__ void spmm256_csr_kernel(const float* __restrict__ X,
                                   float* __restrict__ S, int N) {
    int row = blockIdx.x * 4 + (threadIdx.x >> 6);
    if (row >= N) return;
    int lane = threadIdx.x & 63;
    int beg = g_rowptr[row];
    int end = g_rowptr[row + 1];

    float4 acc = make_float4(0.f, 0.f, 0.f, 0.f);
    int e = beg;
    for (; e + 4 <= end; e += 4) {
        #pragma unroll
        for (int u = 0; u < 4; u++) {
            unsigned long long p = g_edge[e + u];
            int c = (int)(p & 0xFFFFFFFFull);
            float v = __uint_as_float((unsigned)(p >> 32));
            float4 x = *(const float4*)(X + (size_t)c * D1 + lane * 4);
            acc.x = fmaf(v, x.x, acc.x);
            acc.y = fmaf(v, x.y, acc.y);
            acc.z = fmaf(v, x.z, acc.z);
            acc.w = fmaf(v, x.w, acc.w);
        }
    }
    for (; e < end; e++) {
        unsigned long long p = g_edge[e];
        int c = (int)(p & 0xFFFFFFFFull);
        float v = __uint_as_float((unsigned)(p >> 32));
        float4 x = *(const float4*)(X + (size_t)c * D1 + lane * 4);
        acc.x = fmaf(v, x.x, acc.x);
        acc.y = fmaf(v, x.y, acc.y);
        acc.z = fmaf(v, x.z, acc.z);
        acc.w = fmaf(v, x.w, acc.w);
    }
    *(float4*)(S + (size_t)row * D1 + lane * 4) = acc;
}

// ---------------- layer2 ----------------
__global__ void layer2_kernel(const float* __restrict__ S1, const float* __restrict__ b1,
                              const float* __restrict__ W2, float* __restrict__ X2, int N) {
    __shared__ float sW[D1 * D2];
    __shared__ float sb[D1];
    for (int i = threadIdx.x; i < D1 * D2; i += blockDim.x) sW[i] = W2[i];
    for (int i = threadIdx.x; i < D1; i += blockDim.x) sb[i] = b1[i];
    __syncthreads();

    int row = blockIdx.x * blockDim.x + threadIdx.x;
    if (row >= N) return;

    float acc[D2] = {};
    const float4* s = (const float4*)(S1 + (size_t)row * D1);
    #pragma unroll 4
    for (int k4 = 0; k4 < D1 / 4; k4++) {
        float4 v = s[k4];
        int k = k4 * 4;
        float h0 = fmaxf(v.x + sb[k + 0], 0.f);
        float h1 = fmaxf(v.y + sb[k + 1], 0.f);
        float h2 = fmaxf(v.z + sb[k + 2], 0.f);
        float h3 = fmaxf(v.w + sb[k + 3], 0.f);
        #pragma unroll
        for (int j = 0; j < D2; j++) {
            acc[j] = fmaf(h0, sW[(k + 0) * D2 + j],
                     fmaf(h1, sW[(k + 1) * D2 + j],
                     fmaf(h2, sW[(k + 2) * D2 + j],
                     fmaf(h3, sW[(k + 3) * D2 + j], acc[j]))));
        }
    }
    float4* o = (float4*)(X2 + (size_t)row * D2);
    #pragma unroll
    for (int q = 0; q < 4; q++)
        o[q] = make_float4(acc[q * 4 + 0], acc[q * 4 + 1], acc[q * 4 + 2], acc[q * 4 + 3]);
}

// ---------------- SpMM d=16 + degree (CSR) ----------------
__global__ void spmm16_csr_kernel(const float* __restrict__ X2,
                                  float* __restrict__ S2, float* __restrict__ D, int N) {
    int row = blockIdx.x * 16 + (threadIdx.x >> 4);
    if (row >= N) return;
    int j = threadIdx.x & 15;
    int beg = g_rowptr[row];
    int end = g_rowptr[row + 1];

    float acc = 0.f, wsum = 0.f;
    for (int e = beg; e < end; e++) {
        unsigned long long p = g_edge[e];
        int c = (int)(p & 0xFFFFFFFFull);
        float v = __uint_as_float((unsigned)(p >> 32));
        acc = fmaf(v, X2[(size_t)c * D2 + j], acc);
        wsum += v;
    }
    S2[(size_t)row * D2 + j] = acc;
    if (j == 0) D[row] = wsum;
}

// ---------------- head ----------------
__global__ void head_kernel(const float* __restrict__ S2, const float* __restrict__ b2,
                            const float* __restrict__ Wl, const float* __restrict__ bl,
                            const float* __restrict__ D, float* __restrict__ Y,
                            float* __restrict__ Gamma, int N) {
    __shared__ float sW[D2 * D2];
    __shared__ float sb2[D2];
    __shared__ float sbl[D2];
    __shared__ float sG[D2];
    if (threadIdx.x < D2 * D2) sW[threadIdx.x] = Wl[threadIdx.x];
    if (threadIdx.x < D2) {
        sb2[threadIdx.x] = b2[threadIdx.x];
        sbl[threadIdx.x] = bl[threadIdx.x];
        sG[threadIdx.x] = 0.f;
    }
    __syncthreads();

    int row = blockIdx.x * blockDim.x + threadIdx.x;
    if (row < N) {
        float h2[D2];
        const float4* s = (const float4*)(S2 + (size_t)row * D2);
        #pragma unroll
        for (int q = 0; q < 4; q++) {
            float4 v = s[q];
            h2[q * 4 + 0] = fmaxf(v.x + sb2[q * 4 + 0], 0.f);
            h2[q * 4 + 1] = fmaxf(v.y + sb2[q * 4 + 1], 0.f);
            h2[q * 4 + 2] = fmaxf(v.z + sb2[q * 4 + 2], 0.f);
            h2[q * 4 + 3] = fmaxf(v.w + sb2[q * 4 + 3], 0.f);
        }
        float h3[D2];
        #pragma unroll
        for (int j = 0; j < D2; j++) {
            float t = sbl[j];
            #pragma unroll
            for (int k = 0; k < D2; k++) t = fmaf(h2[k], sW[k * D2 + j], t);
            h3[j] = fmaxf(t, 0.f);
        }
        float m = h3[0];
        #pragma unroll
        for (int j = 1; j < D2; j++) m = fmaxf(m, h3[j]);
        float sum = 0.f;
        float y[D2];
        #pragma unroll
        for (int j = 0; j < D2; j++) { y[j] = __expf(h3[j] - m); sum += y[j]; }
        float inv = 1.0f / sum;
        float4* o = (float4*)(Y + (size_t)row * D2);
        #pragma unroll
        for (int q = 0; q < 4; q++) {
            o[q] = make_float4(y[q * 4 + 0] * inv, y[q * 4 + 1] * inv,
                               y[q * 4 + 2] * inv, y[q * 4 + 3] * inv);
        }
        float d = D[row];
        #pragma unroll
        for (int j = 0; j < D2; j++) atomicAdd(&sG[j], y[j] * inv * d);
    }
    __syncthreads();
    if (threadIdx.x < D2) atomicAdd(&Gamma[threadIdx.x], sG[threadIdx.x]);
}

// ---------------- loss ----------------
__global__ void loss_kernel(const int* __restrict__ ridx,
                            const int* __restrict__ cidx,
                            const float* __restrict__ w,
                            const float* __restrict__ Y,
                            const float* __restrict__ Gamma,
                            float* __restrict__ out, int E) {
    __shared__ float sGinv[D2];
    if (threadIdx.x < D2) sGinv[threadIdx.x] = 1.0f / Gamma[threadIdx.x];
    __syncthreads();

    int e = blockIdx.x * blockDim.x + threadIdx.x;
    float acc = 0.f;
    if (e < E) {
        int r = ridx[e];
        int c = cidx[e];
        float v = w[e];
        const float4* yr = (const float4*)(Y + (size_t)r * D2);
        const float4* yc = (const float4*)(Y + (size_t)c * D2);
        #pragma unroll
        for (int q = 0; q < 4; q++) {
            float4 a = yr[q];
            float4 b = yc[q];
            acc += a.x * sGinv[q * 4 + 0] * (1.f - b.x)
                 + a.y * sGinv[q * 4 + 1] * (1.f - b.y)
                 + a.z * sGinv[q * 4 + 2] * (1.f - b.z)
                 + a.w * sGinv[q * 4 + 3] * (1.f - b.w);
        }
        acc *= v;
    }
    #pragma unroll
    for (int off = 16; off > 0; off >>= 1)
        acc += __shfl_down_sync(0xFFFFFFFFu, acc, off);
    if ((threadIdx.x & 31) == 0) atomicAdd(out, acc);
}

// ---------------- launch ----------------
extern "C" void kernel_launch(void* const* d_in, const int* in_sizes, int n_in,
                              void* d_out, int out_size) {
    const float*     H    = (const float*)d_in[0];
    const void*      ei   = d_in[1];
    const float*     ev   = (const float*)d_in[2];
    const float*     W1   = (const float*)d_in[3];
    const float*     b1   = (const float*)d_in[4];
    const float*     W2   = (const float*)d_in[5];
    const float*     b2   = (const float*)d_in[6];
    const float*     Wl   = (const float*)d_in[7];
    const float*     bl   = (const float*)d_in[8];
    float* out = (float*)d_out;

    int N = in_sizes[0] / D0;          // 50000
    int E = in_sizes[2];               // 1600000

    void *pX1, *pS1, *pX2, *pS2, *pY, *pD, *pG, *pR, *pC, *pCnt, *pW1T;
    cudaGetSymbolAddress(&pX1, g_X1);
    cudaGetSymbolAddress(&pS1, g_S1);
    cudaGetSymbolAddress(&pX2, g_X2);
    cudaGetSymbolAddress(&pS2, g_S2);
    cudaGetSymbolAddress(&pY,  g_Y);
    cudaGetSymbolAddress(&pD,  g_D);
    cudaGetSymbolAddress(&pG,  g_Gamma);
    cudaGetSymbolAddress(&pR,  g_row);
    cudaGetSymbolAddress(&pC,  g_col);
    cudaGetSymbolAddress(&pCnt, g_cnt);
    cudaGetSymbolAddress(&pW1T, g_W1T);
    const int* ridx = (const int*)pR;
    const int* cidx = (const int*)pC;

    cudaMemsetAsync(pCnt, 0, N_NODES * sizeof(int));
    cudaMemsetAsync(pG,  0, D2 * sizeof(float));
    cudaMemsetAsync(out, 0, sizeof(float));

    // 0) CSR build + W1 transpose
    detect_idx_kernel<<<1, 1>>>(ei);
    convert_idx_kernel<<<(E + 255) / 256, 256>>>(ei, E);
    scan_kernel<<<1, 1024>>>(N, E);
    scatter_kernel<<<(E + 255) / 256, 256>>>(ev, E);
    transpose_w1<<<dim3(D1 / 32, D0 / 32), dim3(32, 8)>>>(W1, (float*)pW1T);

    // 1) X1 = H @ W1  (mma.sync tf32, 3-pass split precision)
    {
        dim3 grid(D1 / 128, (N + 127) / 128);
        gemm1_mma_kernel<<<grid, 256>>>(H, (const float*)pW1T, (float*)pX1, N);
    }
    // 2) S1 = spmm(X1)
    spmm256_csr_kernel<<<(N + 3) / 4, 256>>>((const float*)pX1, (float*)pS1, N);
    // 3) X2 = relu(S1 + b1) @ W2
    layer2_kernel<<<(N + 255) / 256, 256>>>((const float*)pS1, b1, W2, (float*)pX2, N);
    // 4) S2 = spmm(X2), D = degree
    spmm16_csr_kernel<<<(N + 15) / 16, 256>>>((const float*)pX2, (float*)pS2, (float*)pD, N);
    // 5) head
    head_kernel<<<(N + 255) / 256, 256>>>((const float*)pS2, b2, Wl, bl,
                                          (const float*)pD, (float*)pY, (float*)pG, N);
    // 6) loss
    loss_kernel<<<(E + 255) / 256, 256>>>(ridx, cidx, ev, (const float*)pY,
                                          (const float*)pG, out, E);
}